// round 12
// baseline (speedup 1.0000x reference)
#include <cuda_runtime.h>
#include <cuda_bf16.h>
#include <cstdint>

// Embedding row-gather via async bulk-copy DMA (register-free datapath).
// out[t, :] = weights[ids[t], :]
// ids: int32[16384], weights: float[50257,1024] (4KB rows), out: float[16384,1024]
//
// R6: ptxas refuses to keep >1 gathered row live in registers (R4/R5 both
// regs=32, MLP~1-2, DRAM ~50%). So bypass the RF: each CTA issues 8x 4KB
// cp.async.bulk global->smem (one mbarrier, expect_tx=32KB), waits, then
// 8x 4KB cp.async.bulk smem->global. The bulk engine provides the MLP.

#define ROW_BYTES 4096
#define ROWS_PER_CTA 8
#define TILE_BYTES (ROWS_PER_CTA * ROW_BYTES)

__device__ __forceinline__ uint32_t smem_u32(const void* p) {
    uint32_t a;
    asm("{ .reg .u64 t; cvta.to.shared.u64 t, %1; cvt.u32.u64 %0, t; }"
        : "=r"(a) : "l"(p));
    return a;
}

__global__ __launch_bounds__(32) void embed_bulk_kernel(
    const int* __restrict__ ids,
    const char* __restrict__ weights,
    char* __restrict__ out,
    int n_tokens)
{
    __shared__ alignas(128) char buf[TILE_BYTES];
    __shared__ alignas(8) unsigned long long mbar;

    if (threadIdx.x != 0) return;  // single-thread CTA control; no bar.sync used

    int base = blockIdx.x * ROWS_PER_CTA;
    uint32_t mbar_a = smem_u32(&mbar);
    uint32_t buf_a  = smem_u32(buf);

    // mbarrier init (generic proxy) -> visible to async proxy
    asm volatile("mbarrier.init.shared.b64 [%0], 1;" :: "r"(mbar_a) : "memory");
    asm volatile("fence.proxy.async.shared::cta;" ::: "memory");

    // Expect the full 32KB, then fire 8 independent 4KB DMA gathers.
    asm volatile("mbarrier.arrive.expect_tx.shared.b64 _, [%0], %1;"
                 :: "r"(mbar_a), "r"((uint32_t)TILE_BYTES) : "memory");
#pragma unroll
    for (int r = 0; r < ROWS_PER_CTA; r++) {
        const char* src = weights + (size_t)ids[base + r] * ROW_BYTES;
        asm volatile(
            "cp.async.bulk.shared::cta.global.mbarrier::complete_tx::bytes "
            "[%0], [%1], %2, [%3];"
            :: "r"(buf_a + r * ROW_BYTES), "l"(src),
               "r"((uint32_t)ROW_BYTES), "r"(mbar_a)
            : "memory");
    }

    // Wait for all 8 loads (phase parity 0).
    {
        uint32_t done;
        asm volatile(
            "{\n\t"
            ".reg .pred p;\n\t"
            "mbarrier.try_wait.parity.shared.b64 p, [%1], 0;\n\t"
            "selp.b32 %0, 1, 0, p;\n\t"
            "}"
            : "=r"(done) : "r"(mbar_a) : "memory");
        if (!done) {
            asm volatile(
                "{\n\t"
                ".reg .pred P1;\n\t"
                "WL_%=:\n\t"
                "mbarrier.try_wait.parity.shared.b64 P1, [%0], 0, 0x989680;\n\t"
                "@P1 bra.uni WD_%=;\n\t"
                "bra.uni WL_%=;\n\t"
                "WD_%=:\n\t"
                "}"
                :: "r"(mbar_a) : "memory");
        }
    }

    // 8x 4KB DMA scatter-out (coalesced, contiguous destination rows).
#pragma unroll
    for (int r = 0; r < ROWS_PER_CTA; r++) {
        char* dst = out + (size_t)(base + r) * ROW_BYTES;
        asm volatile(
            "cp.async.bulk.global.shared::cta.bulk_group [%0], [%1], %2;"
            :: "l"(dst), "r"(buf_a + r * ROW_BYTES), "r"((uint32_t)ROW_BYTES)
            : "memory");
    }
    asm volatile("cp.async.bulk.commit_group;" ::: "memory");
    asm volatile("cp.async.bulk.wait_group 0;" ::: "memory");
}

extern "C" void kernel_launch(void* const* d_in, const int* in_sizes, int n_in,
                              void* d_out, int out_size) {
    const int* ids = (const int*)d_in[0];
    const char* w = (const char*)d_in[1];
    char* out = (char*)d_out;
    int n_tokens = in_sizes[0];  // 16384, divisible by 8
    int grid = n_tokens / ROWS_PER_CTA;  // 2048
    embed_bulk_kernel<<<grid, 32>>>(ids, w, out, n_tokens);
}

// round 13
// speedup vs baseline: 1.0128x; 1.0128x over previous
#include <cuda_runtime.h>
#include <cuda_bf16.h>
#include <cstdint>

// Embedding row-gather, pipelined async bulk-copy.
// out[t, :] = weights[ids[t], :]
// ids: int32[16384], weights: float[50257,1024] (4KB rows), out: float[16384,1024]
//
// R13: R12 showed the one-shot bulk kernel serializes load-phase / store-phase
// per CTA -> ~50% read duty cycle (DRAM 47.9%, same wall as register path).
// Fix: 4-stage ring of 4KB rows. Prologue issues 4 DMA gathers; each loop
// iteration waits one stage, bulk-stores it, and refills the stage with the
// row 4 ahead. wait_group.read 0 only drains the store's SMEM reads (fast),
// so global stores remain fire-and-forget and loads stream continuously.

#define ROW_BYTES 4096
#define NS 4
#define ROWS_PER_CTA 8

__device__ __forceinline__ uint32_t smem_u32(const void* p) {
    uint32_t a;
    asm("{ .reg .u64 t; cvta.to.shared.u64 t, %1; cvt.u32.u64 %0, t; }"
        : "=r"(a) : "l"(p));
    return a;
}

__device__ __forceinline__ void mbar_wait(uint32_t mbar_a, uint32_t parity) {
    uint32_t done;
    asm volatile(
        "{\n\t"
        ".reg .pred p;\n\t"
        "mbarrier.try_wait.parity.shared.b64 p, [%1], %2;\n\t"
        "selp.b32 %0, 1, 0, p;\n\t"
        "}"
        : "=r"(done) : "r"(mbar_a), "r"(parity) : "memory");
    if (!done) {
        asm volatile(
            "{\n\t"
            ".reg .pred P1;\n\t"
            "WL_%=:\n\t"
            "mbarrier.try_wait.parity.shared.b64 P1, [%0], %1, 0x989680;\n\t"
            "@P1 bra.uni WD_%=;\n\t"
            "bra.uni WL_%=;\n\t"
            "WD_%=:\n\t"
            "}"
            :: "r"(mbar_a), "r"(parity) : "memory");
    }
}

__global__ __launch_bounds__(32) void embed_pipe_kernel(
    const int* __restrict__ ids,
    const char* __restrict__ weights,
    char* __restrict__ out,
    int n_tokens)
{
    __shared__ alignas(128) char buf[NS * ROW_BYTES];
    __shared__ alignas(8) unsigned long long mbar[NS];

    if (threadIdx.x != 0) return;  // single control thread; no bar.sync anywhere

    int base = blockIdx.x * ROWS_PER_CTA;

    // Row indices up front (independent scalar loads).
    int row[ROWS_PER_CTA];
#pragma unroll
    for (int r = 0; r < ROWS_PER_CTA; r++)
        row[r] = ids[base + r];

    uint32_t buf_a = smem_u32(buf);
    uint32_t mb_a[NS];
#pragma unroll
    for (int s = 0; s < NS; s++) {
        mb_a[s] = smem_u32(&mbar[s]);
        asm volatile("mbarrier.init.shared.b64 [%0], 1;" :: "r"(mb_a[s]) : "memory");
    }
    asm volatile("fence.proxy.async.shared::cta;" ::: "memory");

    // Prologue: fill all NS stages with gathered 4KB DMA loads.
#pragma unroll
    for (int s = 0; s < NS; s++) {
        const char* src = weights + (size_t)row[s] * ROW_BYTES;
        asm volatile("mbarrier.arrive.expect_tx.shared.b64 _, [%0], %1;"
                     :: "r"(mb_a[s]), "r"((uint32_t)ROW_BYTES) : "memory");
        asm volatile(
            "cp.async.bulk.shared::cta.global.mbarrier::complete_tx::bytes "
            "[%0], [%1], %2, [%3];"
            :: "r"(buf_a + s * ROW_BYTES), "l"(src),
               "r"((uint32_t)ROW_BYTES), "r"(mb_a[s])
            : "memory");
    }

    // Main loop: drain stage r%NS, store it out, refill with row r+NS.
#pragma unroll
    for (int r = 0; r < ROWS_PER_CTA; r++) {
        int s = r & (NS - 1);
        uint32_t parity = (r / NS) & 1;

        mbar_wait(mb_a[s], parity);

        char* dst = out + (size_t)(base + r) * ROW_BYTES;
        asm volatile(
            "cp.async.bulk.global.shared::cta.bulk_group [%0], [%1], %2;"
            :: "l"(dst), "r"(buf_a + s * ROW_BYTES), "r"((uint32_t)ROW_BYTES)
            : "memory");
        asm volatile("cp.async.bulk.commit_group;" ::: "memory");

        int nr = r + NS;
        if (nr < ROWS_PER_CTA) {
            // Only wait for SMEM-read completion of committed stores (fast);
            // global-side store completion stays asynchronous.
            asm volatile("cp.async.bulk.wait_group.read 0;" ::: "memory");
            const char* src = weights + (size_t)row[nr] * ROW_BYTES;
            asm volatile("mbarrier.arrive.expect_tx.shared.b64 _, [%0], %1;"
                         :: "r"(mb_a[s]), "r"((uint32_t)ROW_BYTES) : "memory");
            asm volatile(
                "cp.async.bulk.shared::cta.global.mbarrier::complete_tx::bytes "
                "[%0], [%1], %2, [%3];"
                :: "r"(buf_a + s * ROW_BYTES), "l"(src),
                   "r"((uint32_t)ROW_BYTES), "r"(mb_a[s])
                : "memory");
        }
    }

    // Ensure all stores fully complete before CTA exit.
    asm volatile("cp.async.bulk.wait_group 0;" ::: "memory");
}

extern "C" void kernel_launch(void* const* d_in, const int* in_sizes, int n_in,
                              void* d_out, int out_size) {
    const int* ids = (const int*)d_in[0];
    const char* w = (const char*)d_in[1];
    char* out = (char*)d_out;
    int n_tokens = in_sizes[0];  // 16384, divisible by ROWS_PER_CTA
    int grid = n_tokens / ROWS_PER_CTA;  // 2048
    embed_pipe_kernel<<<grid, 32>>>(ids, w, out, n_tokens);
}